// round 9
// baseline (speedup 1.0000x reference)
#include <cuda_runtime.h>
#include <cuda_fp16.h>
#include <cstdint>
#include <math.h>

typedef unsigned int u32;

#define NN 32768
#define EE 262144
#define BB 8
#define HH 128
#define LL 6

// ---------------- scratch (device globals; no allocation) ----------------
__device__ __align__(16) float g_h[NN*HH];
__device__ __align__(16) float g_t1[NN*HH];
__device__ __align__(16) __half g_Ph[NN*HH];
__device__ __align__(16) __half g_Qh[NN*HH];
__device__ __align__(16) float g_R[NN*HH];
__device__ __align__(16) float g_agg[NN*HH];
__device__ __align__(16) __half g_Wm2h[LL*HH*HH];
__device__ float g_px[NN];
__device__ float g_pt[NN];
__device__ int   g_icnt[NN];
__device__ int   g_cur[NN];
__device__ float g_inv[NN];
__device__ int   g_ssrc[EE];
__device__ int   g_stgt[EE];
__device__ float g_meanb[BB*HH];
__device__ float g_sqb[BB*HH];
__device__ float g_gcnt[BB];

__device__ __forceinline__ float swishf(float x) {
    return x / (1.f + __expf(-x));
}

__device__ __forceinline__ u32 smem_u32(const void* p) {
    return (u32)__cvta_generic_to_shared(p);
}

__device__ __forceinline__ void ldsm4(u32& r0, u32& r1, u32& r2, u32& r3, u32 a) {
    asm volatile("ldmatrix.sync.aligned.m8n8.x4.shared.b16 {%0,%1,%2,%3}, [%4];"
                 : "=r"(r0), "=r"(r1), "=r"(r2), "=r"(r3) : "r"(a));
}

__device__ __forceinline__ void ldsm4t(u32& r0, u32& r1, u32& r2, u32& r3, u32 a) {
    asm volatile("ldmatrix.sync.aligned.m8n8.x4.trans.shared.b16 {%0,%1,%2,%3}, [%4];"
                 : "=r"(r0), "=r"(r1), "=r"(r2), "=r"(r3) : "r"(a));
}

__device__ __forceinline__ void mma16816(float* c, u32 a0, u32 a1, u32 a2, u32 a3,
                                         u32 b0, u32 b1) {
    asm volatile("mma.sync.aligned.m16n8k16.row.col.f32.f16.f16.f32 "
                 "{%0,%1,%2,%3}, {%4,%5,%6,%7}, {%8,%9}, {%0,%1,%2,%3};"
                 : "+f"(c[0]), "+f"(c[1]), "+f"(c[2]), "+f"(c[3])
                 : "r"(a0), "r"(a1), "r"(a2), "r"(a3), "r"(b0), "r"(b1));
}

// ---------------- zero / prep ----------------
__global__ void zero_prep() {
    int i = blockIdx.x * 256 + threadIdx.x;
    if (i < NN) g_icnt[i] = 0;
    if (i < BB) g_gcnt[i] = 0.f;
}

__global__ void zero_agg() {
    int i = blockIdx.x * 256 + threadIdx.x;
    ((float4*)g_agg)[i] = make_float4(0.f, 0.f, 0.f, 0.f);
}

__global__ void zero_stats() {
    int i = threadIdx.x + blockIdx.x * 256;
    if (i < BB*HH) { g_meanb[i] = 0.f; g_sqb[i] = 0.f; }
}

__global__ void prep_node(const float* __restrict__ pos, const int* __restrict__ batch) {
    int i = blockIdx.x * 256 + threadIdx.x;
    if (i < NN) {
        g_pt[i] = pos[2*i]   * 0.25f;
        g_px[i] = pos[2*i+1] * 0.0625f;
        atomicAdd(&g_gcnt[batch[i]], 1.f);
    }
}

__global__ void prep_edge(const int* __restrict__ eidx) {
    int e = blockIdx.x * 256 + threadIdx.x;
    if (e < EE) atomicAdd(&g_icnt[eidx[EE + e]], 1);
}

// single-block exclusive scan of g_icnt -> g_cur (32768 = 1024 threads x 32)
__global__ void scan_off() {
    __shared__ int ss[1024];
    int t = threadIdx.x;
    int base = t * 32;
    int loc[32];
    int s = 0;
    #pragma unroll
    for (int j = 0; j < 32; j++) { loc[j] = s; s += g_icnt[base + j]; }
    ss[t] = s;
    __syncthreads();
    for (int d = 1; d < 1024; d <<= 1) {
        int v = (t >= d) ? ss[t - d] : 0;
        __syncthreads();
        ss[t] += v;
        __syncthreads();
    }
    int cb = (t == 0) ? 0 : ss[t - 1];
    #pragma unroll
    for (int j = 0; j < 32; j++) g_cur[base + j] = cb + loc[j];
}

__global__ void edge_sort(const int* __restrict__ eidx) {
    int e = blockIdx.x * 256 + threadIdx.x;
    if (e < EE) {
        int s = eidx[e];
        int t = eidx[EE + e];
        int p = atomicAdd(&g_cur[t], 1);
        g_ssrc[p] = s;
        g_stgt[p] = t;
    }
}

__global__ void fin_cnt() {
    int i = blockIdx.x * 256 + threadIdx.x;
    if (i < NN) g_inv[i] = 1.f / (float)max(g_icnt[i], 1);
}

// convert all 6 layers of Wm2 to fp16 (49152 half2)
__global__ void convert_wm2(const float* __restrict__ Wm2) {
    int i = blockIdx.x * 256 + threadIdx.x;   // over LL*HH*HH/2
    float2 v = ((const float2*)Wm2)[i];
    ((__half2*)g_Wm2h)[i] = __floats2half2_rn(v.x, v.y);
}

// ---------------- small per-node kernels ----------------
__global__ void encoder1(const float* __restrict__ u, const float* __restrict__ We1,
                         const float* __restrict__ be1) {
    __shared__ float s[27];
    int n = blockIdx.x;
    int t = threadIdx.x;
    if (t < 25)       s[t]  = u[n*25 + t];
    else if (t == 25) s[25] = g_px[n];
    else if (t == 26) s[26] = g_pt[n];
    __syncthreads();
    float a = __ldg(&be1[t]);
    #pragma unroll
    for (int k = 0; k < 27; k++) a += s[k] * __ldg(&We1[k*128 + t]);
    g_t1[n*128 + t] = swishf(a);
}

__global__ void rkern(const float* __restrict__ u, const float* __restrict__ Wm1l) {
    __shared__ float s[26];
    int n = blockIdx.x;
    int t = threadIdx.x;
    if (t < 25)       s[t]  = u[n*25 + t];
    else if (t == 25) s[25] = g_px[n];
    __syncthreads();
    float a = 0.f;
    #pragma unroll
    for (int k = 0; k < 25; k++) a += s[k] * __ldg(&Wm1l[(256+k)*128 + t]);
    a += s[25] * __ldg(&Wm1l[281*128 + t]);
    g_R[n*128 + t] = a;
}

// ---------------- tensor-core node GEMM: 64 rows x 128 cols ----------------
// modes: 0: swish(acc+b) ->out    1: acc+R+pt*wx+b ->outh(fp16)   2: acc-R ->outh(fp16)
//        3: swish(acc+pt*wx+b) ->out [K=256, A2 scaled]            4: out += swish(acc+b)
__global__ void mlp16(const float* __restrict__ A, const float* __restrict__ A2,
                      const float* __restrict__ W, const float* __restrict__ bias,
                      const float* __restrict__ Rm, const float* __restrict__ wx,
                      float* __restrict__ out, __half* __restrict__ outh,
                      int K, int mode) {
    extern __shared__ __align__(16) char smbuf[];
    __half* Wh = (__half*)smbuf;            // K x 136
    __half* Ah = Wh + K*136;                // 64 x (K+8)
    const int PA = K + 8;

    int tid = threadIdx.x;
    int r0g = blockIdx.x * 64;

    for (int i = tid; i < K*32; i += 256) {
        int k = i >> 5;
        int c4 = (i & 31) << 2;
        float4 v = *(const float4*)&W[k*128 + c4];
        __half2* dst = (__half2*)&Wh[k*136 + c4];
        dst[0] = __floats2half2_rn(v.x, v.y);
        dst[1] = __floats2half2_rn(v.z, v.w);
    }
    int kq = K >> 2;
    int sh = (K == 256) ? 6 : 5;
    for (int i = tid; i < (64 << sh); i += 256) {
        int r  = i >> sh;
        int k4 = (i & (kq - 1)) << 2;
        int row = r0g + r;
        float4 v;
        if (k4 < 128) {
            v = *(const float4*)&A[row*128 + k4];
        } else {
            v = *(const float4*)&A2[row*128 + (k4 - 128)];
            float s = g_inv[row];
            v.x *= s; v.y *= s; v.z *= s; v.w *= s;
        }
        __half2* dst = (__half2*)&Ah[r*PA + k4];
        dst[0] = __floats2half2_rn(v.x, v.y);
        dst[1] = __floats2half2_rn(v.z, v.w);
    }
    __syncthreads();

    int w = tid >> 5;
    int lane = tid & 31;
    int wm = (w & 3) * 16;
    int wn = (w >> 2) * 64;
    int grp = lane >> 2;
    int qt  = lane & 3;
    int lr = lane & 7;
    int lm = lane >> 3;

    float acc[8][4];
    #pragma unroll
    for (int j = 0; j < 8; j++) {
        #pragma unroll
        for (int i = 0; i < 4; i++) acc[j][i] = 0.f;
    }

    u32 a_base = smem_u32(Ah) + (u32)(((wm + (lm & 1)*8 + lr)*PA + (lm >> 1)*8) * 2);
    u32 b_base = smem_u32(Wh) + (u32)((((lm & 1)*8 + lr)*136 + wn + (lm >> 1)*8) * 2);

    int kit = K >> 4;
    for (int kk = 0; kk < kit; kk++) {
        u32 a0, a1, a2, a3;
        ldsm4(a0, a1, a2, a3, a_base + (u32)(kk*32));
        #pragma unroll
        for (int j = 0; j < 4; j++) {
            u32 b0, b1, b2, b3;
            ldsm4t(b0, b1, b2, b3, b_base + (u32)(kk*4352 + j*32));
            mma16816(acc[2*j],     a0, a1, a2, a3, b0, b1);
            mma16816(acc[2*j + 1], a0, a1, a2, a3, b2, b3);
        }
    }

    #pragma unroll
    for (int j = 0; j < 8; j++) {
        int col = wn + j*8 + 2*qt;
        int r0 = r0g + wm + grp;
        int r1 = r0 + 8;
        float a0 = acc[j][0], a1 = acc[j][1], a2 = acc[j][2], a3 = acc[j][3];
        if (mode == 0) {
            float o0 = swishf(a0 + __ldg(&bias[col]));
            float o1 = swishf(a1 + __ldg(&bias[col+1]));
            float o2 = swishf(a2 + __ldg(&bias[col]));
            float o3 = swishf(a3 + __ldg(&bias[col+1]));
            *(float2*)&out[r0*128 + col] = make_float2(o0, o1);
            *(float2*)&out[r1*128 + col] = make_float2(o2, o3);
        } else if (mode == 1) {
            float pt0 = g_pt[r0], pt1 = g_pt[r1];
            float o0 = a0 + Rm[r0*128 + col]   + pt0*__ldg(&wx[col])   + __ldg(&bias[col]);
            float o1 = a1 + Rm[r0*128 + col+1] + pt0*__ldg(&wx[col+1]) + __ldg(&bias[col+1]);
            float o2 = a2 + Rm[r1*128 + col]   + pt1*__ldg(&wx[col])   + __ldg(&bias[col]);
            float o3 = a3 + Rm[r1*128 + col+1] + pt1*__ldg(&wx[col+1]) + __ldg(&bias[col+1]);
            *(__half2*)&outh[r0*128 + col] = __floats2half2_rn(o0, o1);
            *(__half2*)&outh[r1*128 + col] = __floats2half2_rn(o2, o3);
        } else if (mode == 2) {
            float o0 = a0 - Rm[r0*128 + col];
            float o1 = a1 - Rm[r0*128 + col+1];
            float o2 = a2 - Rm[r1*128 + col];
            float o3 = a3 - Rm[r1*128 + col+1];
            *(__half2*)&outh[r0*128 + col] = __floats2half2_rn(o0, o1);
            *(__half2*)&outh[r1*128 + col] = __floats2half2_rn(o2, o3);
        } else if (mode == 3) {
            float pt0 = g_pt[r0], pt1 = g_pt[r1];
            float o0 = swishf(a0 + pt0*__ldg(&wx[col])   + __ldg(&bias[col]));
            float o1 = swishf(a1 + pt0*__ldg(&wx[col+1]) + __ldg(&bias[col+1]));
            float o2 = swishf(a2 + pt1*__ldg(&wx[col])   + __ldg(&bias[col]));
            float o3 = swishf(a3 + pt1*__ldg(&wx[col+1]) + __ldg(&bias[col+1]));
            *(float2*)&out[r0*128 + col] = make_float2(o0, o1);
            *(float2*)&out[r1*128 + col] = make_float2(o2, o3);
        } else {
            float o0 = out[r0*128 + col]   + swishf(a0 + __ldg(&bias[col]));
            float o1 = out[r0*128 + col+1] + swishf(a1 + __ldg(&bias[col+1]));
            float o2 = out[r1*128 + col]   + swishf(a2 + __ldg(&bias[col]));
            float o3 = out[r1*128 + col+1] + swishf(a3 + __ldg(&bias[col+1]));
            *(float2*)&out[r0*128 + col] = make_float2(o0, o1);
            *(float2*)&out[r1*128 + col] = make_float2(o2, o3);
        }
    }
}

// ---------------- fused edge kernel: persistent W, sorted edges, segmented scatter ----------------
// smem: Wh 128x136 half (34816B) | Mh 64x136 half (17408B) | Cs 64x128 f32 (32768B) | st,ss 64+64 int
#define EDGE_SMEM (34816 + 17408 + 32768 + 512)
#define EDGE_GRID 512
__global__ void edge_kernel(const __half* __restrict__ Whg,
                            const float* __restrict__ bm2l) {
    extern __shared__ __align__(16) char smbuf[];
    __half* Wh = (__half*)smbuf;                       // 128 x 136
    __half* Mh = (__half*)(smbuf + 34816);             // 64 x 136
    float*  Cs = (float*)(smbuf + 34816 + 17408);      // 64 x 128
    int*    st = (int*)(smbuf + 34816 + 17408 + 32768);
    int*    se = st + 64;

    int tid = threadIdx.x;

    // stage W once (fp16 global -> smem pitch 136)
    for (int i = tid; i < 128*16; i += 256) {
        int r = i >> 4;
        int c8 = (i & 15) << 3;
        uint4 v = *(const uint4*)&Whg[r*128 + c8];
        *(uint4*)&Wh[r*136 + c8] = v;
    }
    __syncthreads();

    int w = tid >> 5;
    int lane = tid & 31;
    int wm = (w & 3) * 16;
    int wn = (w >> 2) * 64;
    int grp = lane >> 2;
    int qt  = lane & 3;
    int lr = lane & 7;
    int lm = lane >> 3;

    u32 a_base = smem_u32(Mh) + (u32)(((wm + (lm & 1)*8 + lr)*136 + (lm >> 1)*8) * 2);
    u32 b_base = smem_u32(Wh) + (u32)((((lm & 1)*8 + lr)*136 + wn + (lm >> 1)*8) * 2);

    int acol = tid >> 1;            // aggregation column
    int arow0 = (tid & 1) * 32;     // aggregation row range start

    for (int tile = blockIdx.x; tile < EE/64; tile += EDGE_GRID) {
        int e0 = tile * 64;
        if (tid < 64) {
            st[tid] = g_stgt[e0 + tid];
            se[tid] = g_ssrc[e0 + tid];
        }
        __syncthreads();

        // gather + first swish -> fp16 messages
        for (int i = tid; i < 64*16; i += 256) {
            int e = i >> 4;
            int c8 = (i & 15) << 3;
            uint4 pv = *(const uint4*)&g_Ph[st[e]*128 + c8];
            uint4 qv = *(const uint4*)&g_Qh[se[e]*128 + c8];
            __half2* ph = (__half2*)&pv;
            __half2* qh = (__half2*)&qv;
            uint4 ov;
            __half2* oh = (__half2*)&ov;
            #pragma unroll
            for (int k2 = 0; k2 < 4; k2++) {
                float2 p2 = __half22float2(ph[k2]);
                float2 q2 = __half22float2(qh[k2]);
                oh[k2] = __floats2half2_rn(swishf(p2.x + q2.x), swishf(p2.y + q2.y));
            }
            *(uint4*)&Mh[e*136 + c8] = ov;
        }
        __syncthreads();

        float acc[8][4];
        #pragma unroll
        for (int j = 0; j < 8; j++) {
            #pragma unroll
            for (int i = 0; i < 4; i++) acc[j][i] = 0.f;
        }

        #pragma unroll
        for (int kk = 0; kk < 8; kk++) {
            u32 a0, a1, a2, a3;
            ldsm4(a0, a1, a2, a3, a_base + (u32)(kk*32));
            #pragma unroll
            for (int j = 0; j < 4; j++) {
                u32 b0, b1, b2, b3;
                ldsm4t(b0, b1, b2, b3, b_base + (u32)(kk*4352 + j*32));
                mma16816(acc[2*j],     a0, a1, a2, a3, b0, b1);
                mma16816(acc[2*j + 1], a0, a1, a2, a3, b2, b3);
            }
        }

        // second swish + bias -> Cs
        int er0 = wm + grp;
        int er1 = er0 + 8;
        #pragma unroll
        for (int j = 0; j < 8; j++) {
            int col = wn + j*8 + 2*qt;
            float b0v = __ldg(&bm2l[col]);
            float b1v = __ldg(&bm2l[col + 1]);
            Cs[er0*128 + col]     = swishf(acc[j][0] + b0v);
            Cs[er0*128 + col + 1] = swishf(acc[j][1] + b1v);
            Cs[er1*128 + col]     = swishf(acc[j][2] + b0v);
            Cs[er1*128 + col + 1] = swishf(acc[j][3] + b1v);
        }
        __syncthreads();

        // segmented scatter: runs of equal tgt -> one atomic per run per col-half
        {
            float a = 0.f;
            int curt = st[arow0];
            for (int r = arow0; r < arow0 + 32; r++) {
                int t2 = st[r];
                if (t2 != curt) {
                    atomicAdd(&g_agg[curt*128 + acol], a);
                    a = 0.f;
                    curt = t2;
                }
                a += Cs[r*128 + acol];
            }
            atomicAdd(&g_agg[curt*128 + acol], a);
        }
        __syncthreads();
    }
}

// ---------------- per-batch norm ----------------
__global__ void norm_reduce(const int* __restrict__ batch) {
    int c = threadIdx.x;
    int base = blockIdx.x * 128;
    float s = 0.f, q = 0.f;
    for (int r = 0; r < 128; r++) {
        float v = g_h[(base + r)*128 + c];
        s += v;
        q += v*v;
    }
    int b = batch[base];
    atomicAdd(&g_meanb[b*128 + c], s);
    atomicAdd(&g_sqb[b*128 + c], q);
}

__global__ void norm_apply(const int* __restrict__ batch) {
    int i = blockIdx.x * 256 + threadIdx.x;
    int node = i >> 7;
    int c = i & 127;
    int b = batch[node];
    float gi = 1.f / g_gcnt[b];
    float m = g_meanb[b*128 + c] * gi;
    float var = g_sqb[b*128 + c] * gi - m*m;
    g_h[i] = (g_h[i] - m) * rsqrtf(var + 1e-5f);
}

// ---------------- conv decoder ----------------
__global__ void decoder(const float* __restrict__ u,
                        const float* __restrict__ Wc1, const float* __restrict__ bc1,
                        const float* __restrict__ Wc2, const float* __restrict__ bc2,
                        float* __restrict__ out) {
    __shared__ float hr[128];
    __shared__ float c1[8*38];
    int n = blockIdx.x;
    int tid = threadIdx.x;
    for (int i = tid; i < 128; i += 64) hr[i] = g_h[n*128 + i];
    __syncthreads();
    for (int i = tid; i < 8*38; i += 64) {
        int ch = i / 38;
        int p = i % 38;
        float a = __ldg(&bc1[ch]);
        #pragma unroll
        for (int k = 0; k < 16; k++) a += hr[3*p + k] * __ldg(&Wc1[ch*16 + k]);
        c1[i] = swishf(a);
    }
    __syncthreads();
    if (tid < 25) {
        float a = __ldg(&bc2[0]);
        #pragma unroll
        for (int c = 0; c < 8; c++) {
            #pragma unroll
            for (int k = 0; k < 14; k++)
                a += c1[c*38 + tid + k] * __ldg(&Wc2[c*14 + k]);
        }
        float dt = 4.0f / 250.0f;
        out[n*25 + tid] = u[n*25 + 24] + (float)(tid + 1) * dt * a;
    }
}

// ---------------- host ----------------
extern "C" void kernel_launch(void* const* d_in, const int* in_sizes, int n_in,
                              void* d_out, int out_size) {
    const float* u     = (const float*)d_in[0];
    const float* pos   = (const float*)d_in[1];
    const int*   eidx  = (const int*)d_in[2];
    const int*   batch = (const int*)d_in[3];
    const float* We1 = (const float*)d_in[4];
    const float* be1 = (const float*)d_in[5];
    const float* We2 = (const float*)d_in[6];
    const float* be2 = (const float*)d_in[7];
    const float* Wm1 = (const float*)d_in[8];
    const float* bm1 = (const float*)d_in[9];
    const float* Wm2 = (const float*)d_in[10];
    const float* bm2 = (const float*)d_in[11];
    const float* Wu1 = (const float*)d_in[12];
    const float* bu1 = (const float*)d_in[13];
    const float* Wu2 = (const float*)d_in[14];
    const float* bu2 = (const float*)d_in[15];
    const float* Wc1 = (const float*)d_in[16];
    const float* bc1 = (const float*)d_in[17];
    const float* Wc2 = (const float*)d_in[18];
    const float* bc2 = (const float*)d_in[19];
    float* out = (float*)d_out;

    void *a_h = 0, *a_t1 = 0, *a_Ph = 0, *a_Qh = 0, *a_R = 0, *a_agg = 0, *a_wm2h = 0;
    cudaGetSymbolAddress(&a_h,    g_h);
    cudaGetSymbolAddress(&a_t1,   g_t1);
    cudaGetSymbolAddress(&a_Ph,   g_Ph);
    cudaGetSymbolAddress(&a_Qh,   g_Qh);
    cudaGetSymbolAddress(&a_R,    g_R);
    cudaGetSymbolAddress(&a_agg,  g_agg);
    cudaGetSymbolAddress(&a_wm2h, g_Wm2h);
    float*  h    = (float*)a_h;
    float*  t1   = (float*)a_t1;
    __half* Ph   = (__half*)a_Ph;
    __half* Qh   = (__half*)a_Qh;
    float*  R    = (float*)a_R;
    float*  agg  = (float*)a_agg;
    __half* Wm2h = (__half*)a_wm2h;

    int MLP_SMEM_MAX = (256*136 + 64*264) * 2;   // K=256 case
    int MLP_SMEM_128 = (128*136 + 64*136) * 2;
    cudaFuncSetAttribute(mlp16, cudaFuncAttributeMaxDynamicSharedMemorySize, MLP_SMEM_MAX);
    cudaFuncSetAttribute(edge_kernel, cudaFuncAttributeMaxDynamicSharedMemorySize, EDGE_SMEM);

    convert_wm2<<<(LL*HH*HH/2)/256, 256>>>(Wm2);
    zero_prep<<<NN/256, 256>>>();
    prep_node<<<NN/256, 256>>>(pos, batch);
    prep_edge<<<EE/256, 256>>>(eidx);
    scan_off<<<1, 1024>>>();
    edge_sort<<<EE/256, 256>>>(eidx);
    fin_cnt<<<NN/256, 256>>>();

    encoder1<<<NN, 128>>>(u, We1, be1);
    mlp16<<<NN/64, 256, MLP_SMEM_128>>>(t1, (const float*)0, We2, be2, (const float*)0, (const float*)0, h, (__half*)0, 128, 0);

    for (int l = 0; l < LL; l++) {
        const float* Wm1l = Wm1 + (size_t)l * 283 * 128;
        const float* Wu1l = Wu1 + (size_t)l * 257 * 128;
        const float* Wu2l = Wu2 + (size_t)l * 128 * 128;

        rkern<<<NN, 128>>>(u, Wm1l);
        mlp16<<<NN/64, 256, MLP_SMEM_128>>>(h, (const float*)0, Wm1l, bm1 + l*128, R, Wm1l + 282*128, (float*)0, Ph, 128, 1);
        mlp16<<<NN/64, 256, MLP_SMEM_128>>>(h, (const float*)0, Wm1l + 128*128, (const float*)0, R, (const float*)0, (float*)0, Qh, 128, 2);

        zero_agg<<<(NN*HH/4)/256, 256>>>();
        edge_kernel<<<EDGE_GRID, 256, EDGE_SMEM>>>(Wm2h + (size_t)l*HH*HH, bm2 + l*128);

        mlp16<<<NN/64, 256, MLP_SMEM_MAX>>>(h, agg, Wu1l, bu1 + l*128, (const float*)0, Wu1l + 256*128, t1, (__half*)0, 256, 3);
        mlp16<<<NN/64, 256, MLP_SMEM_128>>>(t1, (const float*)0, Wu2l, bu2 + l*128, (const float*)0, (const float*)0, h, (__half*)0, 128, 4);

        zero_stats<<<(BB*HH + 255)/256, 256>>>();
        norm_reduce<<<NN/128, 128>>>(batch);
        norm_apply<<<(NN*HH)/256, 256>>>(batch);
    }

    decoder<<<NN, 64>>>(u, Wc1, bc1, Wc2, bc2, out);
}

// round 10
// speedup vs baseline: 1.2137x; 1.2137x over previous
#include <cuda_runtime.h>
#include <cuda_fp16.h>
#include <cstdint>
#include <math.h>

typedef unsigned int u32;

#define NN 32768
#define EE 262144
#define BB 8
#define HH 128
#define LL 6

// ---------------- scratch (device globals; no allocation) ----------------
__device__ __align__(16) float g_h[NN*HH];
__device__ __align__(16) float g_t1[NN*HH];
__device__ __align__(16) __half g_Ph[NN*HH];
__device__ __align__(16) __half g_Qh[NN*HH];
__device__ __align__(16) float g_R[NN*HH];
__device__ __align__(16) float g_agg[NN*HH];
__device__ __align__(16) __half g_Wm2h[LL*HH*HH];
__device__ float g_px[NN];
__device__ float g_pt[NN];
__device__ int   g_icnt[NN];
__device__ float g_inv[NN];
__device__ float g_meanb[BB*HH];
__device__ float g_sqb[BB*HH];
__device__ float g_gcnt[BB];

__device__ __forceinline__ float swishf(float x) {
    return x / (1.f + __expf(-x));
}

__device__ __forceinline__ u32 smem_u32(const void* p) {
    return (u32)__cvta_generic_to_shared(p);
}

__device__ __forceinline__ void ldsm4(u32& r0, u32& r1, u32& r2, u32& r3, u32 a) {
    asm volatile("ldmatrix.sync.aligned.m8n8.x4.shared.b16 {%0,%1,%2,%3}, [%4];"
                 : "=r"(r0), "=r"(r1), "=r"(r2), "=r"(r3) : "r"(a));
}

__device__ __forceinline__ void ldsm4t(u32& r0, u32& r1, u32& r2, u32& r3, u32 a) {
    asm volatile("ldmatrix.sync.aligned.m8n8.x4.trans.shared.b16 {%0,%1,%2,%3}, [%4];"
                 : "=r"(r0), "=r"(r1), "=r"(r2), "=r"(r3) : "r"(a));
}

__device__ __forceinline__ void mma16816(float* c, u32 a0, u32 a1, u32 a2, u32 a3,
                                         u32 b0, u32 b1) {
    asm volatile("mma.sync.aligned.m16n8k16.row.col.f32.f16.f16.f32 "
                 "{%0,%1,%2,%3}, {%4,%5,%6,%7}, {%8,%9}, {%0,%1,%2,%3};"
                 : "+f"(c[0]), "+f"(c[1]), "+f"(c[2]), "+f"(c[3])
                 : "r"(a0), "r"(a1), "r"(a2), "r"(a3), "r"(b0), "r"(b1));
}

// ---------------- zero / prep ----------------
__global__ void zero_prep() {
    int i = blockIdx.x * 256 + threadIdx.x;
    if (i < NN) g_icnt[i] = 0;
    if (i < BB) g_gcnt[i] = 0.f;
}

__global__ void zero_agg() {
    int i = blockIdx.x * 256 + threadIdx.x;
    ((float4*)g_agg)[i] = make_float4(0.f, 0.f, 0.f, 0.f);
}

__global__ void zero_stats() {
    int i = threadIdx.x + blockIdx.x * 256;
    if (i < BB*HH) { g_meanb[i] = 0.f; g_sqb[i] = 0.f; }
}

__global__ void prep_node(const float* __restrict__ pos, const int* __restrict__ batch) {
    int i = blockIdx.x * 256 + threadIdx.x;
    if (i < NN) {
        g_pt[i] = pos[2*i]   * 0.25f;
        g_px[i] = pos[2*i+1] * 0.0625f;
        atomicAdd(&g_gcnt[batch[i]], 1.f);
    }
}

__global__ void prep_edge(const int* __restrict__ eidx) {
    int e = blockIdx.x * 256 + threadIdx.x;
    if (e < EE) atomicAdd(&g_icnt[eidx[EE + e]], 1);
}

__global__ void fin_cnt() {
    int i = blockIdx.x * 256 + threadIdx.x;
    if (i < NN) g_inv[i] = 1.f / (float)max(g_icnt[i], 1);
}

// convert all 6 layers of Wm2 to fp16 (49152 half2)
__global__ void convert_wm2(const float* __restrict__ Wm2) {
    int i = blockIdx.x * 256 + threadIdx.x;   // over LL*HH*HH/2
    float2 v = ((const float2*)Wm2)[i];
    ((__half2*)g_Wm2h)[i] = __floats2half2_rn(v.x, v.y);
}

// ---------------- small per-node kernels ----------------
__global__ void encoder1(const float* __restrict__ u, const float* __restrict__ We1,
                         const float* __restrict__ be1) {
    __shared__ float s[27];
    int n = blockIdx.x;
    int t = threadIdx.x;
    if (t < 25)       s[t]  = u[n*25 + t];
    else if (t == 25) s[25] = g_px[n];
    else if (t == 26) s[26] = g_pt[n];
    __syncthreads();
    float a = __ldg(&be1[t]);
    #pragma unroll
    for (int k = 0; k < 27; k++) a += s[k] * __ldg(&We1[k*128 + t]);
    g_t1[n*128 + t] = swishf(a);
}

__global__ void rkern(const float* __restrict__ u, const float* __restrict__ Wm1l) {
    __shared__ float s[26];
    int n = blockIdx.x;
    int t = threadIdx.x;
    if (t < 25)       s[t]  = u[n*25 + t];
    else if (t == 25) s[25] = g_px[n];
    __syncthreads();
    float a = 0.f;
    #pragma unroll
    for (int k = 0; k < 25; k++) a += s[k] * __ldg(&Wm1l[(256+k)*128 + t]);
    a += s[25] * __ldg(&Wm1l[281*128 + t]);
    g_R[n*128 + t] = a;
}

// ---------------- tensor-core node GEMM: 64 rows x 128 cols ----------------
// modes: 0: swish(acc+b) ->out    1: acc+R+pt*wx+b ->outh(fp16)   2: acc-R ->outh(fp16)
//        3: swish(acc+pt*wx+b) ->out [K=256, A2 scaled]            4: out += swish(acc+b)
__global__ void mlp16(const float* __restrict__ A, const float* __restrict__ A2,
                      const float* __restrict__ W, const float* __restrict__ bias,
                      const float* __restrict__ Rm, const float* __restrict__ wx,
                      float* __restrict__ out, __half* __restrict__ outh,
                      int K, int mode) {
    extern __shared__ __align__(16) char smbuf[];
    __half* Wh = (__half*)smbuf;            // K x 136
    __half* Ah = Wh + K*136;                // 64 x (K+8)
    const int PA = K + 8;

    int tid = threadIdx.x;
    int r0g = blockIdx.x * 64;

    for (int i = tid; i < K*32; i += 256) {
        int k = i >> 5;
        int c4 = (i & 31) << 2;
        float4 v = *(const float4*)&W[k*128 + c4];
        __half2* dst = (__half2*)&Wh[k*136 + c4];
        dst[0] = __floats2half2_rn(v.x, v.y);
        dst[1] = __floats2half2_rn(v.z, v.w);
    }
    int kq = K >> 2;
    int sh = (K == 256) ? 6 : 5;
    for (int i = tid; i < (64 << sh); i += 256) {
        int r  = i >> sh;
        int k4 = (i & (kq - 1)) << 2;
        int row = r0g + r;
        float4 v;
        if (k4 < 128) {
            v = *(const float4*)&A[row*128 + k4];
        } else {
            v = *(const float4*)&A2[row*128 + (k4 - 128)];
            float s = g_inv[row];
            v.x *= s; v.y *= s; v.z *= s; v.w *= s;
        }
        __half2* dst = (__half2*)&Ah[r*PA + k4];
        dst[0] = __floats2half2_rn(v.x, v.y);
        dst[1] = __floats2half2_rn(v.z, v.w);
    }
    __syncthreads();

    int w = tid >> 5;
    int lane = tid & 31;
    int wm = (w & 3) * 16;
    int wn = (w >> 2) * 64;
    int grp = lane >> 2;
    int qt  = lane & 3;
    int lr = lane & 7;
    int lm = lane >> 3;

    float acc[8][4];
    #pragma unroll
    for (int j = 0; j < 8; j++) {
        #pragma unroll
        for (int i = 0; i < 4; i++) acc[j][i] = 0.f;
    }

    u32 a_base = smem_u32(Ah) + (u32)(((wm + (lm & 1)*8 + lr)*PA + (lm >> 1)*8) * 2);
    u32 b_base = smem_u32(Wh) + (u32)((((lm & 1)*8 + lr)*136 + wn + (lm >> 1)*8) * 2);

    int kit = K >> 4;
    for (int kk = 0; kk < kit; kk++) {
        u32 a0, a1, a2, a3;
        ldsm4(a0, a1, a2, a3, a_base + (u32)(kk*32));
        #pragma unroll
        for (int j = 0; j < 4; j++) {
            u32 b0, b1, b2, b3;
            ldsm4t(b0, b1, b2, b3, b_base + (u32)(kk*4352 + j*32));
            mma16816(acc[2*j],     a0, a1, a2, a3, b0, b1);
            mma16816(acc[2*j + 1], a0, a1, a2, a3, b2, b3);
        }
    }

    #pragma unroll
    for (int j = 0; j < 8; j++) {
        int col = wn + j*8 + 2*qt;
        int r0 = r0g + wm + grp;
        int r1 = r0 + 8;
        float a0 = acc[j][0], a1 = acc[j][1], a2 = acc[j][2], a3 = acc[j][3];
        if (mode == 0) {
            float o0 = swishf(a0 + __ldg(&bias[col]));
            float o1 = swishf(a1 + __ldg(&bias[col+1]));
            float o2 = swishf(a2 + __ldg(&bias[col]));
            float o3 = swishf(a3 + __ldg(&bias[col+1]));
            *(float2*)&out[r0*128 + col] = make_float2(o0, o1);
            *(float2*)&out[r1*128 + col] = make_float2(o2, o3);
        } else if (mode == 1) {
            float pt0 = g_pt[r0], pt1 = g_pt[r1];
            float o0 = a0 + Rm[r0*128 + col]   + pt0*__ldg(&wx[col])   + __ldg(&bias[col]);
            float o1 = a1 + Rm[r0*128 + col+1] + pt0*__ldg(&wx[col+1]) + __ldg(&bias[col+1]);
            float o2 = a2 + Rm[r1*128 + col]   + pt1*__ldg(&wx[col])   + __ldg(&bias[col]);
            float o3 = a3 + Rm[r1*128 + col+1] + pt1*__ldg(&wx[col+1]) + __ldg(&bias[col+1]);
            *(__half2*)&outh[r0*128 + col] = __floats2half2_rn(o0, o1);
            *(__half2*)&outh[r1*128 + col] = __floats2half2_rn(o2, o3);
        } else if (mode == 2) {
            float o0 = a0 - Rm[r0*128 + col];
            float o1 = a1 - Rm[r0*128 + col+1];
            float o2 = a2 - Rm[r1*128 + col];
            float o3 = a3 - Rm[r1*128 + col+1];
            *(__half2*)&outh[r0*128 + col] = __floats2half2_rn(o0, o1);
            *(__half2*)&outh[r1*128 + col] = __floats2half2_rn(o2, o3);
        } else if (mode == 3) {
            float pt0 = g_pt[r0], pt1 = g_pt[r1];
            float o0 = swishf(a0 + pt0*__ldg(&wx[col])   + __ldg(&bias[col]));
            float o1 = swishf(a1 + pt0*__ldg(&wx[col+1]) + __ldg(&bias[col+1]));
            float o2 = swishf(a2 + pt1*__ldg(&wx[col])   + __ldg(&bias[col]));
            float o3 = swishf(a3 + pt1*__ldg(&wx[col+1]) + __ldg(&bias[col+1]));
            *(float2*)&out[r0*128 + col] = make_float2(o0, o1);
            *(float2*)&out[r1*128 + col] = make_float2(o2, o3);
        } else {
            float o0 = out[r0*128 + col]   + swishf(a0 + __ldg(&bias[col]));
            float o1 = out[r0*128 + col+1] + swishf(a1 + __ldg(&bias[col+1]));
            float o2 = out[r1*128 + col]   + swishf(a2 + __ldg(&bias[col]));
            float o3 = out[r1*128 + col+1] + swishf(a3 + __ldg(&bias[col+1]));
            *(float2*)&out[r0*128 + col] = make_float2(o0, o1);
            *(float2*)&out[r1*128 + col] = make_float2(o2, o3);
        }
    }
}

// ---------------- fused edge kernel: persistent W (8 tiles/block), fp16 gathers, direct atomics ----------------
// smem: Wh 128x136 half (34816B) | Mh 64x136 half (17408B) | st,ss 64+64 int (512B)  => ~52.7KB -> 4 blocks/SM
#define EDGE_SMEM (34816 + 17408 + 512)
#define EDGE_GRID 512
__global__ void edge_kernel(const int* __restrict__ eidx,
                            const __half* __restrict__ Whg,
                            const float* __restrict__ bm2l) {
    extern __shared__ __align__(16) char smbuf[];
    __half* Wh = (__half*)smbuf;                       // 128 x 136
    __half* Mh = (__half*)(smbuf + 34816);             // 64 x 136
    int*    st = (int*)(smbuf + 34816 + 17408);
    int*    se = st + 64;

    int tid = threadIdx.x;

    // stage W once per block (fp16 global -> smem pitch 136)
    for (int i = tid; i < 128*16; i += 256) {
        int r = i >> 4;
        int c8 = (i & 15) << 3;
        uint4 v = *(const uint4*)&Whg[r*128 + c8];
        *(uint4*)&Wh[r*136 + c8] = v;
    }

    int w = tid >> 5;
    int lane = tid & 31;
    int wm = (w & 3) * 16;
    int wn = (w >> 2) * 64;
    int grp = lane >> 2;
    int qt  = lane & 3;
    int lr = lane & 7;
    int lm = lane >> 3;

    u32 a_base = smem_u32(Mh) + (u32)(((wm + (lm & 1)*8 + lr)*136 + (lm >> 1)*8) * 2);
    u32 b_base = smem_u32(Wh) + (u32)((((lm & 1)*8 + lr)*136 + wn + (lm >> 1)*8) * 2);

    for (int tile = blockIdx.x; tile < EE/64; tile += EDGE_GRID) {
        int e0 = tile * 64;
        __syncthreads();   // protect st/se and Mh from previous iteration readers
        if (tid < 64) {
            se[tid] = eidx[e0 + tid];
            st[tid] = eidx[EE + e0 + tid];
        }
        __syncthreads();

        // gather + first swish -> fp16 messages
        for (int i = tid; i < 64*16; i += 256) {
            int e = i >> 4;
            int c8 = (i & 15) << 3;
            uint4 pv = *(const uint4*)&g_Ph[st[e]*128 + c8];
            uint4 qv = *(const uint4*)&g_Qh[se[e]*128 + c8];
            __half2* ph = (__half2*)&pv;
            __half2* qh = (__half2*)&qv;
            uint4 ov;
            __half2* oh = (__half2*)&ov;
            #pragma unroll
            for (int k2 = 0; k2 < 4; k2++) {
                float2 p2 = __half22float2(ph[k2]);
                float2 q2 = __half22float2(qh[k2]);
                oh[k2] = __floats2half2_rn(swishf(p2.x + q2.x), swishf(p2.y + q2.y));
            }
            *(uint4*)&Mh[e*136 + c8] = ov;
        }
        __syncthreads();

        float acc[8][4];
        #pragma unroll
        for (int j = 0; j < 8; j++) {
            #pragma unroll
            for (int i = 0; i < 4; i++) acc[j][i] = 0.f;
        }

        #pragma unroll
        for (int kk = 0; kk < 8; kk++) {
            u32 a0, a1, a2, a3;
            ldsm4(a0, a1, a2, a3, a_base + (u32)(kk*32));
            #pragma unroll
            for (int j = 0; j < 4; j++) {
                u32 b0, b1, b2, b3;
                ldsm4t(b0, b1, b2, b3, b_base + (u32)(kk*4352 + j*32));
                mma16816(acc[2*j],     a0, a1, a2, a3, b0, b1);
                mma16816(acc[2*j + 1], a0, a1, a2, a3, b2, b3);
            }
        }

        // second swish + direct scatter-add
        int er0 = wm + grp;
        int er1 = er0 + 8;
        int t0 = st[er0];
        int t1 = st[er1];
        #pragma unroll
        for (int j = 0; j < 8; j++) {
            int col = wn + j*8 + 2*qt;
            float b0v = __ldg(&bm2l[col]);
            float b1v = __ldg(&bm2l[col + 1]);
            atomicAdd(&g_agg[t0*128 + col],     swishf(acc[j][0] + b0v));
            atomicAdd(&g_agg[t0*128 + col + 1], swishf(acc[j][1] + b1v));
            atomicAdd(&g_agg[t1*128 + col],     swishf(acc[j][2] + b0v));
            atomicAdd(&g_agg[t1*128 + col + 1], swishf(acc[j][3] + b1v));
        }
    }
}

// ---------------- per-batch norm ----------------
__global__ void norm_reduce(const int* __restrict__ batch) {
    int c = threadIdx.x;
    int base = blockIdx.x * 128;
    float s = 0.f, q = 0.f;
    for (int r = 0; r < 128; r++) {
        float v = g_h[(base + r)*128 + c];
        s += v;
        q += v*v;
    }
    int b = batch[base];
    atomicAdd(&g_meanb[b*128 + c], s);
    atomicAdd(&g_sqb[b*128 + c], q);
}

__global__ void norm_apply(const int* __restrict__ batch) {
    int i = blockIdx.x * 256 + threadIdx.x;
    int node = i >> 7;
    int c = i & 127;
    int b = batch[node];
    float gi = 1.f / g_gcnt[b];
    float m = g_meanb[b*128 + c] * gi;
    float var = g_sqb[b*128 + c] * gi - m*m;
    g_h[i] = (g_h[i] - m) * rsqrtf(var + 1e-5f);
}

// ---------------- conv decoder ----------------
__global__ void decoder(const float* __restrict__ u,
                        const float* __restrict__ Wc1, const float* __restrict__ bc1,
                        const float* __restrict__ Wc2, const float* __restrict__ bc2,
                        float* __restrict__ out) {
    __shared__ float hr[128];
    __shared__ float c1[8*38];
    int n = blockIdx.x;
    int tid = threadIdx.x;
    for (int i = tid; i < 128; i += 64) hr[i] = g_h[n*128 + i];
    __syncthreads();
    for (int i = tid; i < 8*38; i += 64) {
        int ch = i / 38;
        int p = i % 38;
        float a = __ldg(&bc1[ch]);
        #pragma unroll
        for (int k = 0; k < 16; k++) a += hr[3*p + k] * __ldg(&Wc1[ch*16 + k]);
        c1[i] = swishf(a);
    }
    __syncthreads();
    if (tid < 25) {
        float a = __ldg(&bc2[0]);
        #pragma unroll
        for (int c = 0; c < 8; c++) {
            #pragma unroll
            for (int k = 0; k < 14; k++)
                a += c1[c*38 + tid + k] * __ldg(&Wc2[c*14 + k]);
        }
        float dt = 4.0f / 250.0f;
        out[n*25 + tid] = u[n*25 + 24] + (float)(tid + 1) * dt * a;
    }
}

// ---------------- host ----------------
extern "C" void kernel_launch(void* const* d_in, const int* in_sizes, int n_in,
                              void* d_out, int out_size) {
    const float* u     = (const float*)d_in[0];
    const float* pos   = (const float*)d_in[1];
    const int*   eidx  = (const int*)d_in[2];
    const int*   batch = (const int*)d_in[3];
    const float* We1 = (const float*)d_in[4];
    const float* be1 = (const float*)d_in[5];
    const float* We2 = (const float*)d_in[6];
    const float* be2 = (const float*)d_in[7];
    const float* Wm1 = (const float*)d_in[8];
    const float* bm1 = (const float*)d_in[9];
    const float* Wm2 = (const float*)d_in[10];
    const float* bm2 = (const float*)d_in[11];
    const float* Wu1 = (const float*)d_in[12];
    const float* bu1 = (const float*)d_in[13];
    const float* Wu2 = (const float*)d_in[14];
    const float* bu2 = (const float*)d_in[15];
    const float* Wc1 = (const float*)d_in[16];
    const float* bc1 = (const float*)d_in[17];
    const float* Wc2 = (const float*)d_in[18];
    const float* bc2 = (const float*)d_in[19];
    float* out = (float*)d_out;

    void *a_h = 0, *a_t1 = 0, *a_Ph = 0, *a_Qh = 0, *a_R = 0, *a_agg = 0, *a_wm2h = 0;
    cudaGetSymbolAddress(&a_h,    g_h);
    cudaGetSymbolAddress(&a_t1,   g_t1);
    cudaGetSymbolAddress(&a_Ph,   g_Ph);
    cudaGetSymbolAddress(&a_Qh,   g_Qh);
    cudaGetSymbolAddress(&a_R,    g_R);
    cudaGetSymbolAddress(&a_agg,  g_agg);
    cudaGetSymbolAddress(&a_wm2h, g_Wm2h);
    float*  h    = (float*)a_h;
    float*  t1   = (float*)a_t1;
    __half* Ph   = (__half*)a_Ph;
    __half* Qh   = (__half*)a_Qh;
    float*  R    = (float*)a_R;
    float*  agg  = (float*)a_agg;
    __half* Wm2h = (__half*)a_wm2h;

    int MLP_SMEM_MAX = (256*136 + 64*264) * 2;   // K=256 case
    int MLP_SMEM_128 = (128*136 + 64*136) * 2;
    cudaFuncSetAttribute(mlp16, cudaFuncAttributeMaxDynamicSharedMemorySize, MLP_SMEM_MAX);
    cudaFuncSetAttribute(edge_kernel, cudaFuncAttributeMaxDynamicSharedMemorySize, EDGE_SMEM);

    convert_wm2<<<(LL*HH*HH/2)/256, 256>>>(Wm2);
    zero_prep<<<NN/256, 256>>>();
    prep_node<<<NN/256, 256>>>(pos, batch);
    prep_edge<<<EE/256, 256>>>(eidx);
    fin_cnt<<<NN/256, 256>>>();

    encoder1<<<NN, 128>>>(u, We1, be1);
    mlp16<<<NN/64, 256, MLP_SMEM_128>>>(t1, (const float*)0, We2, be2, (const float*)0, (const float*)0, h, (__half*)0, 128, 0);

    for (int l = 0; l < LL; l++) {
        const float* Wm1l = Wm1 + (size_t)l * 283 * 128;
        const float* Wu1l = Wu1 + (size_t)l * 257 * 128;
        const float* Wu2l = Wu2 + (size_t)l * 128 * 128;

        rkern<<<NN, 128>>>(u, Wm1l);
        mlp16<<<NN/64, 256, MLP_SMEM_128>>>(h, (const float*)0, Wm1l, bm1 + l*128, R, Wm1l + 282*128, (float*)0, Ph, 128, 1);
        mlp16<<<NN/64, 256, MLP_SMEM_128>>>(h, (const float*)0, Wm1l + 128*128, (const float*)0, R, (const float*)0, (float*)0, Qh, 128, 2);

        zero_agg<<<(NN*HH/4)/256, 256>>>();
        edge_kernel<<<EDGE_GRID, 256, EDGE_SMEM>>>(eidx, Wm2h + (size_t)l*HH*HH, bm2 + l*128);

        mlp16<<<NN/64, 256, MLP_SMEM_MAX>>>(h, agg, Wu1l, bu1 + l*128, (const float*)0, Wu1l + 256*128, t1, (__half*)0, 256, 3);
        mlp16<<<NN/64, 256, MLP_SMEM_128>>>(t1, (const float*)0, Wu2l, bu2 + l*128, (const float*)0, (const float*)0, h, (__half*)0, 128, 4);

        zero_stats<<<(BB*HH + 255)/256, 256>>>();
        norm_reduce<<<NN/128, 128>>>(batch);
        norm_apply<<<(NN*HH)/256, 256>>>(batch);
    }

    decoder<<<NN, 64>>>(u, Wc1, bc1, Wc2, bc2, out);
}